// round 6
// baseline (speedup 1.0000x reference)
#include <cuda_runtime.h>
#include <cuda_bf16.h>
#include <math.h>

// Problem constants
#define NN   20000          // nodes
#define NE   320000         // edges
#define CC   128            // channels (CIN == H == 128)
#define KK   27             // kernel matrices
#define NB   (KK * CC)      // 3456 = XW columns
#define EDGE_DIM 16
#define MLP_HID  6

// ---------------- static device scratch (no allocations allowed) ----------------
__device__ int   g_idx64;                 // 1 if edge_index is int64
__device__ int   g_src[NE];
__device__ int   g_dst[NE];
__device__ int   g_kbase[NE];
__device__ float g_bw[NE * 8];
__device__ float g_Bmat[3][CC * NB];      // per-layer W reshaped to [Cin, K*H] row-major
__device__ float g_XW[(size_t)NN * NB];   // 276.5 MB
__device__ float g_h[2][NN * CC];         // ping-pong activations

// tap offsets: bit0*1 + bit1*3 + bit2*9
__device__ __constant__ int c_off[8] = {0, 1, 3, 4, 9, 10, 12, 13};

// ---------------- index width detection ----------------
__global__ void detect_idx_kernel(const unsigned int* __restrict__ ei) {
    if (blockIdx.x == 0 && threadIdx.x == 0) {
        int is64 = 1;
        // stay within first 2*NE 32-bit words (valid for both widths)
        for (int i = 0; i < 4096; i++) {
            if (ei[2 * i + 1] != 0u) { is64 = 0; break; }
        }
        g_idx64 = is64;
    }
}

// ---------------- edge preprocessing: MLP + sigmoid + spline basis ----------------
__global__ void edge_pre_kernel(const void* __restrict__ ei_raw,
                                const float* __restrict__ ea,
                                const float* __restrict__ Wp1,
                                const float* __restrict__ bp1,
                                const float* __restrict__ Wp2,
                                const float* __restrict__ bp2) {
    int e = blockIdx.x * blockDim.x + threadIdx.x;
    if (e >= NE) return;

    int s, d;
    if (g_idx64) {
        const long long* p = (const long long*)ei_raw;
        s = (int)p[e];
        d = (int)p[NE + e];
    } else {
        const int* p = (const int*)ei_raw;
        s = p[e];
        d = p[NE + e];
    }
    g_src[e] = s;
    g_dst[e] = d;

    float a[EDGE_DIM];
#pragma unroll
    for (int i = 0; i < EDGE_DIM; i++) a[i] = ea[(size_t)e * EDGE_DIM + i];

    float h[MLP_HID];
#pragma unroll
    for (int j = 0; j < MLP_HID; j++) {
        float z = bp1[j];
#pragma unroll
        for (int i = 0; i < EDGE_DIM; i++) z += a[i] * Wp1[i * MLP_HID + j];
        h[j] = fmaxf(z, 0.0f);
    }

    float fr[3];
    int lo[3];
#pragma unroll
    for (int dd = 0; dd < 3; dd++) {
        float z = bp2[dd];
#pragma unroll
        for (int j = 0; j < MLP_HID; j++) z += h[j] * Wp2[j * 3 + dd];
        float u = 1.0f / (1.0f + expf(-z));
        float v = u * 2.0f;                       // u * (KS-1)
        float l = fminf(fmaxf(floorf(v), 0.0f), 1.0f);
        lo[dd] = (int)l;
        fr[dd] = v - l;
    }
    g_kbase[e] = lo[0] + 3 * lo[1] + 9 * lo[2];

#pragma unroll
    for (int sb = 0; sb < 8; sb++) {
        float w = ((sb & 1) ? fr[0] : 1.0f - fr[0])
                * ((sb & 2) ? fr[1] : 1.0f - fr[1])
                * ((sb & 4) ? fr[2] : 1.0f - fr[2]);
        g_bw[(size_t)e * 8 + sb] = w;
    }
}

// ---------------- reshape W [K,Cin,H] -> Bmat [Cin, K*H] ----------------
__global__ void transpose_w_kernel(const float* __restrict__ W, float* __restrict__ Bmat) {
    int idx = blockIdx.x * blockDim.x + threadIdx.x;
    if (idx >= KK * CC * CC) return;
    int o = idx & 127;
    int rem = idx >> 7;
    int i = rem & 127;
    int k = rem >> 7;
    Bmat[(size_t)i * NB + k * CC + o] = W[idx];
}

// ---------------- fp32 SGEMM, K=128 fixed, C = A@B (+bias) ----------------
__global__ void __launch_bounds__(256)
sgemm128_kernel(const float* __restrict__ A, const float* __restrict__ B,
                const float* __restrict__ bias, float* __restrict__ C,
                int M, int N, int hasBias) {
    __shared__ float As[32][132];
    __shared__ float Bs[32][128];
    int tid = threadIdx.x;
    int bm = blockIdx.y * 128;
    int bn = blockIdx.x * 128;
    int tx = tid & 15, ty = tid >> 4;

    float acc[8][8];
#pragma unroll
    for (int i = 0; i < 8; i++)
#pragma unroll
        for (int j = 0; j < 8; j++) acc[i][j] = 0.0f;

    int arow  = tid >> 3;          // 0..31
    int acol4 = (tid & 7) * 4;     // 0..28
    int brow  = tid >> 5;          // 0..7
    int bcol4 = (tid & 31) * 4;    // 0..124

    for (int kk = 0; kk < 128; kk += 32) {
#pragma unroll
        for (int p = 0; p < 4; p++) {
            int r  = arow + 32 * p;
            int gr = bm + r;
            float4 v = make_float4(0.f, 0.f, 0.f, 0.f);
            if (gr < M) v = *(const float4*)(A + (size_t)gr * 128 + kk + acol4);
            As[acol4 + 0][r] = v.x;
            As[acol4 + 1][r] = v.y;
            As[acol4 + 2][r] = v.z;
            As[acol4 + 3][r] = v.w;
        }
#pragma unroll
        for (int p = 0; p < 4; p++) {
            int kr = brow + 8 * p;
            float4 v = *(const float4*)(B + (size_t)(kk + kr) * N + bn + bcol4);
            *(float4*)&Bs[kr][bcol4] = v;
        }
        __syncthreads();
#pragma unroll
        for (int k = 0; k < 32; k++) {
            float a[8], b[8];
#pragma unroll
            for (int i = 0; i < 8; i++) a[i] = As[k][ty * 8 + i];
#pragma unroll
            for (int j = 0; j < 8; j++) b[j] = Bs[k][tx * 8 + j];
#pragma unroll
            for (int i = 0; i < 8; i++)
#pragma unroll
                for (int j = 0; j < 8; j++) acc[i][j] += a[i] * b[j];
        }
        __syncthreads();
    }

#pragma unroll
    for (int i = 0; i < 8; i++) {
        int gr = bm + ty * 8 + i;
        if (gr >= M) continue;
#pragma unroll
        for (int j = 0; j < 8; j += 4) {
            int gc = bn + tx * 8 + j;
            float4 v = make_float4(acc[i][j], acc[i][j + 1], acc[i][j + 2], acc[i][j + 3]);
            if (hasBias) {
                v.x += bias[gc];
                v.y += bias[gc + 1];
                v.z += bias[gc + 2];
                v.w += bias[gc + 3];
            }
            *(float4*)(C + (size_t)gr * N + gc) = v;
        }
    }
}

// ---------------- edge aggregation: out[dst] += sum_s bw_s * XW[src, k_s, :] ----------------
__global__ void __launch_bounds__(256)
agg_kernel(const float* __restrict__ XW, float* __restrict__ out) {
    int warp = (blockIdx.x * blockDim.x + threadIdx.x) >> 5;
    int lane = threadIdx.x & 31;
    if (warp >= NE) return;
    int e  = warp;
    int s  = g_src[e];
    int d  = g_dst[e];
    int kb = g_kbase[e];

    float wv = 0.0f;
    if (lane < 8) wv = g_bw[(size_t)e * 8 + lane];

    const float* row = XW + (size_t)s * NB + (size_t)kb * CC;
    float4 acc = make_float4(0.f, 0.f, 0.f, 0.f);
#pragma unroll
    for (int t = 0; t < 8; t++) {
        float w = __shfl_sync(0xffffffffu, wv, t);
        float4 v = *(const float4*)(row + c_off[t] * CC + lane * 4);
        acc.x += w * v.x;
        acc.y += w * v.y;
        acc.z += w * v.z;
        acc.w += w * v.w;
    }
    float* op = out + (size_t)d * CC + lane * 4;
    atomicAdd(op + 0, acc.x);
    atomicAdd(op + 1, acc.y);
    atomicAdd(op + 2, acc.z);
    atomicAdd(op + 3, acc.w);
}

// ---------------- in-place ReLU ----------------
__global__ void relu_kernel(float* __restrict__ h) {
    int i = blockIdx.x * blockDim.x + threadIdx.x;
    if (i >= NN * CC / 4) return;
    float4 v = *((float4*)h + i);
    v.x = fmaxf(v.x, 0.f);
    v.y = fmaxf(v.y, 0.f);
    v.z = fmaxf(v.z, 0.f);
    v.w = fmaxf(v.w, 0.f);
    *((float4*)h + i) = v;
}

// ---------------- launch ----------------
extern "C" void kernel_launch(void* const* d_in, const int* in_sizes, int n_in,
                              void* d_out, int out_size) {
    const float* x    = (const float*)d_in[0];
    const void*  ei   = d_in[1];
    const float* ea   = (const float*)d_in[2];
    const float* Wp1  = (const float*)d_in[3];
    const float* bp1  = (const float*)d_in[4];
    const float* Wp2  = (const float*)d_in[5];
    const float* bp2  = (const float*)d_in[6];
    const float* W[3]  = {(const float*)d_in[7],  (const float*)d_in[10], (const float*)d_in[13]};
    const float* Wr[3] = {(const float*)d_in[8],  (const float*)d_in[11], (const float*)d_in[14]};
    const float* b[3]  = {(const float*)d_in[9],  (const float*)d_in[12], (const float*)d_in[15]};
    float* out_final = (float*)d_out;

    float* g_XW_p;    cudaGetSymbolAddress((void**)&g_XW_p, g_XW);
    float* g_h_p;     cudaGetSymbolAddress((void**)&g_h_p, g_h);
    float* g_Bmat_p;  cudaGetSymbolAddress((void**)&g_Bmat_p, g_Bmat);

    // 1) detect edge_index width
    detect_idx_kernel<<<1, 32>>>((const unsigned int*)ei);

    // 2) edge preprocessing (shared by all layers)
    edge_pre_kernel<<<(NE + 255) / 256, 256>>>(ei, ea, Wp1, bp1, Wp2, bp2);

    // 3) reshape weights once
    for (int l = 0; l < 3; l++) {
        transpose_w_kernel<<<(KK * CC * CC + 255) / 256, 256>>>(
            W[l], g_Bmat_p + (size_t)l * CC * NB);
    }

    // 4) three layers
    const float* act = x;
    dim3 gridXW(NB / 128, (NN + 127) / 128);
    dim3 gridRoot(1, (NN + 127) / 128);
    int aggBlocks  = (NE * 32 + 255) / 256;
    int reluBlocks = (NN * CC / 4 + 255) / 256;

    for (int l = 0; l < 3; l++) {
        float* outbuf = (l == 2) ? out_final : (g_h_p + (size_t)l * NN * CC);

        // XW = act @ Bmat_l   [NN,128] @ [128, 3456]
        sgemm128_kernel<<<gridXW, 256>>>(act, g_Bmat_p + (size_t)l * CC * NB,
                                         nullptr, g_XW_p, NN, NB, 0);
        // out = act @ Wr_l + b_l   (initializes outbuf)
        sgemm128_kernel<<<gridRoot, 256>>>(act, Wr[l], b[l], outbuf, NN, CC, 1);

        // out[dst] += sum_s bw * XW[src, k_s]
        agg_kernel<<<aggBlocks, 256>>>(g_XW_p, outbuf);

        if (l < 2) {
            relu_kernel<<<reluBlocks, 256>>>(outbuf);
            act = outbuf;
        }
    }
}

// round 7
// speedup vs baseline: 1.0012x; 1.0012x over previous
#include <cuda_runtime.h>
#include <cuda_bf16.h>
#include <math.h>

// Problem constants
#define NN   20000          // nodes
#define NE   320000         // edges
#define CC   128            // channels (CIN == H == 128)
#define KK   27             // kernel matrices
#define NB   (KK * CC)      // 3456 = XW columns
#define EDGE_DIM 16
#define MLP_HID  6

// ---------------- static device scratch (no allocations allowed) ----------------
__device__ int   g_idx64;                 // 1 if edge_index is int64
__device__ int   g_src[NE];
__device__ int   g_dst[NE];
__device__ int   g_kbase[NE];
__device__ float g_bw[NE * 8];
__device__ float g_Bmat[3][CC * NB];      // per-layer W reshaped to [Cin, K*H] row-major
__device__ float g_XW[(size_t)NN * NB];   // 276.5 MB
__device__ float g_h[2][NN * CC];         // ping-pong activations

// tap offsets: bit0*1 + bit1*3 + bit2*9
__device__ __constant__ int c_off[8] = {0, 1, 3, 4, 9, 10, 12, 13};

// ---------------- index width detection ----------------
__global__ void detect_idx_kernel(const unsigned int* __restrict__ ei) {
    if (blockIdx.x == 0 && threadIdx.x == 0) {
        int is64 = 1;
        // stay within first 2*NE 32-bit words (valid for both widths)
        for (int i = 0; i < 4096; i++) {
            if (ei[2 * i + 1] != 0u) { is64 = 0; break; }
        }
        g_idx64 = is64;
    }
}

// ---------------- edge preprocessing: MLP + sigmoid + spline basis ----------------
__global__ void edge_pre_kernel(const void* __restrict__ ei_raw,
                                const float* __restrict__ ea,
                                const float* __restrict__ Wp1,
                                const float* __restrict__ bp1,
                                const float* __restrict__ Wp2,
                                const float* __restrict__ bp2) {
    int e = blockIdx.x * blockDim.x + threadIdx.x;
    if (e >= NE) return;

    int s, d;
    if (g_idx64) {
        const long long* p = (const long long*)ei_raw;
        s = (int)p[e];
        d = (int)p[NE + e];
    } else {
        const int* p = (const int*)ei_raw;
        s = p[e];
        d = p[NE + e];
    }
    g_src[e] = s;
    g_dst[e] = d;

    float a[EDGE_DIM];
#pragma unroll
    for (int i = 0; i < EDGE_DIM; i++) a[i] = ea[(size_t)e * EDGE_DIM + i];

    float h[MLP_HID];
#pragma unroll
    for (int j = 0; j < MLP_HID; j++) {
        float z = bp1[j];
#pragma unroll
        for (int i = 0; i < EDGE_DIM; i++) z += a[i] * Wp1[i * MLP_HID + j];
        h[j] = fmaxf(z, 0.0f);
    }

    float fr[3];
    int lo[3];
#pragma unroll
    for (int dd = 0; dd < 3; dd++) {
        float z = bp2[dd];
#pragma unroll
        for (int j = 0; j < MLP_HID; j++) z += h[j] * Wp2[j * 3 + dd];
        float u = 1.0f / (1.0f + expf(-z));
        float v = u * 2.0f;                       // u * (KS-1)
        float l = fminf(fmaxf(floorf(v), 0.0f), 1.0f);
        lo[dd] = (int)l;
        fr[dd] = v - l;
    }
    g_kbase[e] = lo[0] + 3 * lo[1] + 9 * lo[2];

#pragma unroll
    for (int sb = 0; sb < 8; sb++) {
        float w = ((sb & 1) ? fr[0] : 1.0f - fr[0])
                * ((sb & 2) ? fr[1] : 1.0f - fr[1])
                * ((sb & 4) ? fr[2] : 1.0f - fr[2]);
        g_bw[(size_t)e * 8 + sb] = w;
    }
}

// ---------------- reshape W [K,Cin,H] -> Bmat [Cin, K*H] ----------------
__global__ void transpose_w_kernel(const float* __restrict__ W, float* __restrict__ Bmat) {
    int idx = blockIdx.x * blockDim.x + threadIdx.x;
    if (idx >= KK * CC * CC) return;
    int o = idx & 127;
    int rem = idx >> 7;
    int i = rem & 127;
    int k = rem >> 7;
    Bmat[(size_t)i * NB + k * CC + o] = W[idx];
}

// ---------------- fp32 SGEMM, K=128 fixed, C = A@B (+bias) ----------------
__global__ void __launch_bounds__(256)
sgemm128_kernel(const float* __restrict__ A, const float* __restrict__ B,
                const float* __restrict__ bias, float* __restrict__ C,
                int M, int N, int hasBias) {
    __shared__ float As[32][132];
    __shared__ float Bs[32][128];
    int tid = threadIdx.x;
    int bm = blockIdx.y * 128;
    int bn = blockIdx.x * 128;
    int tx = tid & 15, ty = tid >> 4;

    float acc[8][8];
#pragma unroll
    for (int i = 0; i < 8; i++)
#pragma unroll
        for (int j = 0; j < 8; j++) acc[i][j] = 0.0f;

    int arow  = tid >> 3;          // 0..31
    int acol4 = (tid & 7) * 4;     // 0..28
    int brow  = tid >> 5;          // 0..7
    int bcol4 = (tid & 31) * 4;    // 0..124

    for (int kk = 0; kk < 128; kk += 32) {
#pragma unroll
        for (int p = 0; p < 4; p++) {
            int r  = arow + 32 * p;
            int gr = bm + r;
            float4 v = make_float4(0.f, 0.f, 0.f, 0.f);
            if (gr < M) v = *(const float4*)(A + (size_t)gr * 128 + kk + acol4);
            As[acol4 + 0][r] = v.x;
            As[acol4 + 1][r] = v.y;
            As[acol4 + 2][r] = v.z;
            As[acol4 + 3][r] = v.w;
        }
#pragma unroll
        for (int p = 0; p < 4; p++) {
            int kr = brow + 8 * p;
            float4 v = *(const float4*)(B + (size_t)(kk + kr) * N + bn + bcol4);
            *(float4*)&Bs[kr][bcol4] = v;
        }
        __syncthreads();
#pragma unroll
        for (int k = 0; k < 32; k++) {
            float a[8], b[8];
#pragma unroll
            for (int i = 0; i < 8; i++) a[i] = As[k][ty * 8 + i];
#pragma unroll
            for (int j = 0; j < 8; j++) b[j] = Bs[k][tx * 8 + j];
#pragma unroll
            for (int i = 0; i < 8; i++)
#pragma unroll
                for (int j = 0; j < 8; j++) acc[i][j] += a[i] * b[j];
        }
        __syncthreads();
    }

#pragma unroll
    for (int i = 0; i < 8; i++) {
        int gr = bm + ty * 8 + i;
        if (gr >= M) continue;
#pragma unroll
        for (int j = 0; j < 8; j += 4) {
            int gc = bn + tx * 8 + j;
            float4 v = make_float4(acc[i][j], acc[i][j + 1], acc[i][j + 2], acc[i][j + 3]);
            if (hasBias) {
                v.x += bias[gc];
                v.y += bias[gc + 1];
                v.z += bias[gc + 2];
                v.w += bias[gc + 3];
            }
            *(float4*)(C + (size_t)gr * N + gc) = v;
        }
    }
}

// ---------------- edge aggregation: out[dst] += sum_s bw_s * XW[src, k_s, :] ----------------
__global__ void __launch_bounds__(256)
agg_kernel(const float* __restrict__ XW, float* __restrict__ out) {
    int warp = (blockIdx.x * blockDim.x + threadIdx.x) >> 5;
    int lane = threadIdx.x & 31;
    if (warp >= NE) return;
    int e  = warp;
    int s  = g_src[e];
    int d  = g_dst[e];
    int kb = g_kbase[e];

    float wv = 0.0f;
    if (lane < 8) wv = g_bw[(size_t)e * 8 + lane];

    const float* row = XW + (size_t)s * NB + (size_t)kb * CC;
    float4 acc = make_float4(0.f, 0.f, 0.f, 0.f);
#pragma unroll
    for (int t = 0; t < 8; t++) {
        float w = __shfl_sync(0xffffffffu, wv, t);
        float4 v = *(const float4*)(row + c_off[t] * CC + lane * 4);
        acc.x += w * v.x;
        acc.y += w * v.y;
        acc.z += w * v.z;
        acc.w += w * v.w;
    }
    float* op = out + (size_t)d * CC + lane * 4;
    atomicAdd(op + 0, acc.x);
    atomicAdd(op + 1, acc.y);
    atomicAdd(op + 2, acc.z);
    atomicAdd(op + 3, acc.w);
}

// ---------------- in-place ReLU ----------------
__global__ void relu_kernel(float* __restrict__ h) {
    int i = blockIdx.x * blockDim.x + threadIdx.x;
    if (i >= NN * CC / 4) return;
    float4 v = *((float4*)h + i);
    v.x = fmaxf(v.x, 0.f);
    v.y = fmaxf(v.y, 0.f);
    v.z = fmaxf(v.z, 0.f);
    v.w = fmaxf(v.w, 0.f);
    *((float4*)h + i) = v;
}

// ---------------- launch ----------------
extern "C" void kernel_launch(void* const* d_in, const int* in_sizes, int n_in,
                              void* d_out, int out_size) {
    const float* x    = (const float*)d_in[0];
    const void*  ei   = d_in[1];
    const float* ea   = (const float*)d_in[2];
    const float* Wp1  = (const float*)d_in[3];
    const float* bp1  = (const float*)d_in[4];
    const float* Wp2  = (const float*)d_in[5];
    const float* bp2  = (const float*)d_in[6];
    const float* W[3]  = {(const float*)d_in[7],  (const float*)d_in[10], (const float*)d_in[13]};
    const float* Wr[3] = {(const float*)d_in[8],  (const float*)d_in[11], (const float*)d_in[14]};
    const float* b[3]  = {(const float*)d_in[9],  (const float*)d_in[12], (const float*)d_in[15]};
    float* out_final = (float*)d_out;

    float* g_XW_p;    cudaGetSymbolAddress((void**)&g_XW_p, g_XW);
    float* g_h_p;     cudaGetSymbolAddress((void**)&g_h_p, g_h);
    float* g_Bmat_p;  cudaGetSymbolAddress((void**)&g_Bmat_p, g_Bmat);

    // 1) detect edge_index width
    detect_idx_kernel<<<1, 32>>>((const unsigned int*)ei);

    // 2) edge preprocessing (shared by all layers)
    edge_pre_kernel<<<(NE + 255) / 256, 256>>>(ei, ea, Wp1, bp1, Wp2, bp2);

    // 3) reshape weights once
    for (int l = 0; l < 3; l++) {
        transpose_w_kernel<<<(KK * CC * CC + 255) / 256, 256>>>(
            W[l], g_Bmat_p + (size_t)l * CC * NB);
    }

    // 4) three layers
    const float* act = x;
    dim3 gridXW(NB / 128, (NN + 127) / 128);
    dim3 gridRoot(1, (NN + 127) / 128);
    int aggBlocks  = (NE * 32 + 255) / 256;
    int reluBlocks = (NN * CC / 4 + 255) / 256;

    for (int l = 0; l < 3; l++) {
        float* outbuf = (l == 2) ? out_final : (g_h_p + (size_t)l * NN * CC);

        // XW = act @ Bmat_l   [NN,128] @ [128, 3456]
        sgemm128_kernel<<<gridXW, 256>>>(act, g_Bmat_p + (size_t)l * CC * NB,
                                         nullptr, g_XW_p, NN, NB, 0);
        // out = act @ Wr_l + b_l   (initializes outbuf)
        sgemm128_kernel<<<gridRoot, 256>>>(act, Wr[l], b[l], outbuf, NN, CC, 1);

        // out[dst] += sum_s bw * XW[src, k_s]
        agg_kernel<<<aggBlocks, 256>>>(g_XW_p, outbuf);

        if (l < 2) {
            relu_kernel<<<reluBlocks, 256>>>(outbuf);
            act = outbuf;
        }
    }
}

// round 9
// speedup vs baseline: 1.3990x; 1.3974x over previous
#include <cuda_runtime.h>
#include <cuda_bf16.h>
#include <math.h>
#include <stdint.h>

// Problem constants
#define NN   20000          // nodes
#define NE   320000         // edges
#define CC   128            // channels (CIN == H == 128)
#define KK   27             // kernel matrices
#define NB   (KK * CC)      // 3456 = XW columns
#define EDGE_DIM 16
#define MLP_HID  6

// ---------------- static device scratch (no allocations allowed) ----------------
__device__ int   g_idx64;                 // 1 if edge_index is int64
__device__ int   g_src[NE];
__device__ int   g_dst[NE];
__device__ int   g_kbase[NE];
__device__ float g_bw[NE * 8];
__device__ float g_XW[(size_t)NN * NB];   // 276.5 MB
__device__ float g_h[2][NN * CC];         // ping-pong activations
__device__ __nv_bfloat16 g_xhi[NN * CC];
__device__ __nv_bfloat16 g_xlo[NN * CC];
__device__ __nv_bfloat16 g_bthi[3][(size_t)NB * CC];  // W transposed to [K*H, Cin], bf16 hi
__device__ __nv_bfloat16 g_btlo[3][(size_t)NB * CC];  // residual lo

// tap offsets: bit0*1 + bit1*3 + bit2*9
__device__ __constant__ int c_off[8] = {0, 1, 3, 4, 9, 10, 12, 13};

// ---------------- index width detection ----------------
__global__ void detect_idx_kernel(const unsigned int* __restrict__ ei) {
    if (blockIdx.x == 0 && threadIdx.x == 0) {
        int is64 = 1;
        for (int i = 0; i < 4096; i++) {
            if (ei[2 * i + 1] != 0u) { is64 = 0; break; }
        }
        g_idx64 = is64;
    }
}

// ---------------- edge preprocessing: MLP + sigmoid + spline basis ----------------
__global__ void edge_pre_kernel(const void* __restrict__ ei_raw,
                                const float* __restrict__ ea,
                                const float* __restrict__ Wp1,
                                const float* __restrict__ bp1,
                                const float* __restrict__ Wp2,
                                const float* __restrict__ bp2) {
    int e = blockIdx.x * blockDim.x + threadIdx.x;
    if (e >= NE) return;

    int s, d;
    if (g_idx64) {
        const long long* p = (const long long*)ei_raw;
        s = (int)p[e];
        d = (int)p[NE + e];
    } else {
        const int* p = (const int*)ei_raw;
        s = p[e];
        d = p[NE + e];
    }
    g_src[e] = s;
    g_dst[e] = d;

    float a[EDGE_DIM];
#pragma unroll
    for (int i = 0; i < EDGE_DIM; i++) a[i] = ea[(size_t)e * EDGE_DIM + i];

    float h[MLP_HID];
#pragma unroll
    for (int j = 0; j < MLP_HID; j++) {
        float z = bp1[j];
#pragma unroll
        for (int i = 0; i < EDGE_DIM; i++) z += a[i] * Wp1[i * MLP_HID + j];
        h[j] = fmaxf(z, 0.0f);
    }

    float fr[3];
    int lo[3];
#pragma unroll
    for (int dd = 0; dd < 3; dd++) {
        float z = bp2[dd];
#pragma unroll
        for (int j = 0; j < MLP_HID; j++) z += h[j] * Wp2[j * 3 + dd];
        float u = 1.0f / (1.0f + expf(-z));
        float v = u * 2.0f;
        float l = fminf(fmaxf(floorf(v), 0.0f), 1.0f);
        lo[dd] = (int)l;
        fr[dd] = v - l;
    }
    g_kbase[e] = lo[0] + 3 * lo[1] + 9 * lo[2];

#pragma unroll
    for (int sb = 0; sb < 8; sb++) {
        float w = ((sb & 1) ? fr[0] : 1.0f - fr[0])
                * ((sb & 2) ? fr[1] : 1.0f - fr[1])
                * ((sb & 4) ? fr[2] : 1.0f - fr[2]);
        g_bw[(size_t)e * 8 + sb] = w;
    }
}

// -------- W [K,Cin,H] fp32 -> Bt [(k*H+o), Cin] bf16 hi/lo (transposed + split) --------
__global__ void conv_w_kernel(const float* __restrict__ W,
                              __nv_bfloat16* __restrict__ hi,
                              __nv_bfloat16* __restrict__ lo) {
    int idx = blockIdx.x * blockDim.x + threadIdx.x;
    if (idx >= KK * CC * CC) return;
    int o = idx & 127;
    int i = (idx >> 7) & 127;
    int k = idx >> 14;
    float v = W[idx];
    __nv_bfloat16 h = __float2bfloat16(v);
    size_t n = (size_t)(k * CC + o) * CC + i;
    hi[n] = h;
    lo[n] = __float2bfloat16(v - __bfloat162float(h));
}

// -------- activation fp32 -> bf16 hi/lo split --------
__global__ void convert_act_kernel(const float* __restrict__ a,
                                   __nv_bfloat16* __restrict__ hi,
                                   __nv_bfloat16* __restrict__ lo) {
    int i = blockIdx.x * blockDim.x + threadIdx.x;
    if (i >= NN * CC) return;
    float v = a[i];
    __nv_bfloat16 h = __float2bfloat16(v);
    hi[i] = h;
    lo[i] = __float2bfloat16(v - __bfloat162float(h));
}

// ================= HMMA (mma.sync bf16) split GEMM: XW = act @ Bmat =================
// C[128x128 tile] = Ahi*Bhi + Alo*Bhi + Ahi*Blo, fp32 accum in registers.
// SMEM: Ahi | Alo | Bhi | Blo, each 128 rows x 128 bf16 (256B/row), XOR-swizzled.
#define TILE_BYTES 32768
#define SM_AHI 0
#define SM_ALO 32768
#define SM_BHI 65536
#define SM_BLO 98304
#define SMEM_TOT 131072

__device__ __forceinline__ uint32_t smem_u32(const void* p) {
    uint32_t a;
    asm("{ .reg .u64 t; cvta.to.shared.u64 t, %1; cvt.u32.u64 %0, t; }" : "=r"(a) : "l"(p));
    return a;
}

// swizzled byte offset within a tile: row 0..127, kc (16B chunk) 0..15
__device__ __forceinline__ uint32_t sw_off(int row, int kc) {
    return (uint32_t)(row * 256 + ((kc ^ (row & 7)) << 4));
}

__device__ __forceinline__ void load_tile(char* smem, int off,
                                          const __nv_bfloat16* __restrict__ src,
                                          int row_base, int row_max, int tid) {
#pragma unroll
    for (int it = 0; it < 8; it++) {
        int idx = it * 256 + tid;
        int row = idx >> 4, kc = idx & 15;
        int grow = row_base + row;
        uint4 v = make_uint4(0u, 0u, 0u, 0u);
        if (grow < row_max)
            v = *(const uint4*)(src + (size_t)grow * CC + kc * 8);
        *(uint4*)(smem + off + sw_off(row, kc)) = v;
    }
}

__device__ __forceinline__ void ldmatrix_x4(uint32_t* r, uint32_t addr) {
    asm volatile("ldmatrix.sync.aligned.m8n8.x4.shared.b16 {%0,%1,%2,%3}, [%4];"
                 : "=r"(r[0]), "=r"(r[1]), "=r"(r[2]), "=r"(r[3]) : "r"(addr));
}

__device__ __forceinline__ void mma16816(float* c, const uint32_t* a, const uint32_t* b) {
    asm volatile(
        "mma.sync.aligned.m16n8k16.row.col.f32.bf16.bf16.f32 "
        "{%0,%1,%2,%3}, {%4,%5,%6,%7}, {%8,%9}, {%0,%1,%2,%3};"
        : "+f"(c[0]), "+f"(c[1]), "+f"(c[2]), "+f"(c[3])
        : "r"(a[0]), "r"(a[1]), "r"(a[2]), "r"(a[3]), "r"(b[0]), "r"(b[1]));
}

__global__ void __launch_bounds__(256, 1)
xw_hmma_kernel(const __nv_bfloat16* __restrict__ xhi,
               const __nv_bfloat16* __restrict__ xlo,
               const __nv_bfloat16* __restrict__ bthi,
               const __nv_bfloat16* __restrict__ btlo,
               float* __restrict__ XW) {
    extern __shared__ __align__(1024) char smem[];
    const int tid  = threadIdx.x;
    const int wid  = tid >> 5;
    const int lane = tid & 31;
    const int bn = blockIdx.x * 128;
    const int bm = blockIdx.y * 128;

    // fill the 4 operand tiles
    load_tile(smem, SM_AHI, xhi,  bm, NN, tid);
    load_tile(smem, SM_ALO, xlo,  bm, NN, tid);
    load_tile(smem, SM_BHI, bthi, bn, NB, tid);
    load_tile(smem, SM_BLO, btlo, bn, NB, tid);
    __syncthreads();

    const uint32_t sbase = smem_u32(smem);

    // warp grid: 2 warp-rows x 4 warp-cols; warp tile 64(m) x 32(n)
    const int m_base = (wid & 1) * 64;
    const int n_base = (wid >> 1) * 32;

    float acc[4][4][4];   // [mtile][ntile][4]
#pragma unroll
    for (int mt = 0; mt < 4; mt++)
#pragma unroll
        for (int nt = 0; nt < 4; nt++)
#pragma unroll
            for (int q = 0; q < 4; q++) acc[mt][nt][q] = 0.0f;

    // ldmatrix lane address components
    // A (x4 covering m16 x k16): rows lanes(0-15)->r0-15, lanes 16-31 -> k+8
    const int a_row_in = (lane & 15);
    const int a_kadd   = (lane >> 4);           // 0 or 1 (8-elem chunks)
    // B (x4 covering two n-tiles x k16)
    const int b_row_in = ((lane >> 4) << 3) + (lane & 7);  // 0-15 across 2 ntiles
    const int b_kadd   = ((lane >> 3) & 1);

    const int passA[3] = {SM_AHI, SM_ALO, SM_AHI};
    const int passB[3] = {SM_BHI, SM_BHI, SM_BLO};

#pragma unroll
    for (int p = 0; p < 3; p++) {
        const uint32_t abase = sbase + passA[p];
        const uint32_t bbase = sbase + passB[p];
#pragma unroll
        for (int ks = 0; ks < 8; ks++) {
            const int kc = ks * 2;   // 16B-chunk index of this k16 step
            uint32_t afrag[4][4];
#pragma unroll
            for (int mt = 0; mt < 4; mt++) {
                int row = m_base + mt * 16 + a_row_in;
                ldmatrix_x4(afrag[mt], abase + sw_off(row, kc + a_kadd));
            }
            uint32_t bfrag[4][2];
#pragma unroll
            for (int g = 0; g < 2; g++) {
                uint32_t r[4];
                int nrow = n_base + g * 16 + b_row_in;
                ldmatrix_x4(r, bbase + sw_off(nrow, kc + b_kadd));
                bfrag[2 * g][0]     = r[0];
                bfrag[2 * g][1]     = r[1];
                bfrag[2 * g + 1][0] = r[2];
                bfrag[2 * g + 1][1] = r[3];
            }
#pragma unroll
            for (int mt = 0; mt < 4; mt++)
#pragma unroll
                for (int nt = 0; nt < 4; nt++)
                    mma16816(acc[mt][nt], afrag[mt], bfrag[nt]);
        }
    }

    // epilogue: direct STG (float2 per acc pair)
    const int qrow = lane >> 2;
    const int qcol = (lane & 3) * 2;
#pragma unroll
    for (int mt = 0; mt < 4; mt++) {
        int r0 = bm + m_base + mt * 16 + qrow;
        int r1 = r0 + 8;
#pragma unroll
        for (int nt = 0; nt < 4; nt++) {
            int col = bn + n_base + nt * 8 + qcol;
            if (r0 < NN)
                *(float2*)(XW + (size_t)r0 * NB + col) =
                    make_float2(acc[mt][nt][0], acc[mt][nt][1]);
            if (r1 < NN)
                *(float2*)(XW + (size_t)r1 * NB + col) =
                    make_float2(acc[mt][nt][2], acc[mt][nt][3]);
        }
    }
}

// ---------------- fp32 SGEMM (root weight path only, small) ----------------
__global__ void __launch_bounds__(256)
sgemm128_kernel(const float* __restrict__ A, const float* __restrict__ B,
                const float* __restrict__ bias, float* __restrict__ C,
                int M, int N, int hasBias) {
    __shared__ float As[32][132];
    __shared__ float Bs[32][128];
    int tid = threadIdx.x;
    int bm = blockIdx.y * 128;
    int bn = blockIdx.x * 128;
    int tx = tid & 15, ty = tid >> 4;

    float acc[8][8];
#pragma unroll
    for (int i = 0; i < 8; i++)
#pragma unroll
        for (int j = 0; j < 8; j++) acc[i][j] = 0.0f;

    int arow  = tid >> 3;
    int acol4 = (tid & 7) * 4;
    int brow  = tid >> 5;
    int bcol4 = (tid & 31) * 4;

    for (int kk = 0; kk < 128; kk += 32) {
#pragma unroll
        for (int p = 0; p < 4; p++) {
            int r  = arow + 32 * p;
            int gr = bm + r;
            float4 v = make_float4(0.f, 0.f, 0.f, 0.f);
            if (gr < M) v = *(const float4*)(A + (size_t)gr * 128 + kk + acol4);
            As[acol4 + 0][r] = v.x;
            As[acol4 + 1][r] = v.y;
            As[acol4 + 2][r] = v.z;
            As[acol4 + 3][r] = v.w;
        }
#pragma unroll
        for (int p = 0; p < 4; p++) {
            int kr = brow + 8 * p;
            float4 v = *(const float4*)(B + (size_t)(kk + kr) * N + bn + bcol4);
            *(float4*)&Bs[kr][bcol4] = v;
        }
        __syncthreads();
#pragma unroll
        for (int k = 0; k < 32; k++) {
            float a[8], b[8];
#pragma unroll
            for (int i = 0; i < 8; i++) a[i] = As[k][ty * 8 + i];
#pragma unroll
            for (int j = 0; j < 8; j++) b[j] = Bs[k][tx * 8 + j];
#pragma unroll
            for (int i = 0; i < 8; i++)
#pragma unroll
                for (int j = 0; j < 8; j++) acc[i][j] += a[i] * b[j];
        }
        __syncthreads();
    }

#pragma unroll
    for (int i = 0; i < 8; i++) {
        int gr = bm + ty * 8 + i;
        if (gr >= M) continue;
#pragma unroll
        for (int j = 0; j < 8; j += 4) {
            int gc = bn + tx * 8 + j;
            float4 v = make_float4(acc[i][j], acc[i][j + 1], acc[i][j + 2], acc[i][j + 3]);
            if (hasBias) {
                v.x += bias[gc];
                v.y += bias[gc + 1];
                v.z += bias[gc + 2];
                v.w += bias[gc + 3];
            }
            *(float4*)(C + (size_t)gr * N + gc) = v;
        }
    }
}

// ---------------- edge aggregation: out[dst] += sum_s bw_s * XW[src, k_s, :] ----------------
__global__ void __launch_bounds__(256)
agg_kernel(const float* __restrict__ XW, float* __restrict__ out) {
    int warp = (blockIdx.x * blockDim.x + threadIdx.x) >> 5;
    int lane = threadIdx.x & 31;
    if (warp >= NE) return;
    int e  = warp;
    int s  = g_src[e];
    int d  = g_dst[e];
    int kb = g_kbase[e];

    float wv = 0.0f;
    if (lane < 8) wv = g_bw[(size_t)e * 8 + lane];

    const float* row = XW + (size_t)s * NB + (size_t)kb * CC;
    float4 acc = make_float4(0.f, 0.f, 0.f, 0.f);
#pragma unroll
    for (int t = 0; t < 8; t++) {
        float w = __shfl_sync(0xffffffffu, wv, t);
        float4 v = *(const float4*)(row + c_off[t] * CC + lane * 4);
        acc.x += w * v.x;
        acc.y += w * v.y;
        acc.z += w * v.z;
        acc.w += w * v.w;
    }
    float* op = out + (size_t)d * CC + lane * 4;
    atomicAdd(op + 0, acc.x);
    atomicAdd(op + 1, acc.y);
    atomicAdd(op + 2, acc.z);
    atomicAdd(op + 3, acc.w);
}

// ---------------- in-place ReLU ----------------
__global__ void relu_kernel(float* __restrict__ h) {
    int i = blockIdx.x * blockDim.x + threadIdx.x;
    if (i >= NN * CC / 4) return;
    float4 v = *((float4*)h + i);
    v.x = fmaxf(v.x, 0.f);
    v.y = fmaxf(v.y, 0.f);
    v.z = fmaxf(v.z, 0.f);
    v.w = fmaxf(v.w, 0.f);
    *((float4*)h + i) = v;
}

// ---------------- launch ----------------
extern "C" void kernel_launch(void* const* d_in, const int* in_sizes, int n_in,
                              void* d_out, int out_size) {
    const float* x    = (const float*)d_in[0];
    const void*  ei   = d_in[1];
    const float* ea   = (const float*)d_in[2];
    const float* Wp1  = (const float*)d_in[3];
    const float* bp1  = (const float*)d_in[4];
    const float* Wp2  = (const float*)d_in[5];
    const float* bp2  = (const float*)d_in[6];
    const float* W[3]  = {(const float*)d_in[7],  (const float*)d_in[10], (const float*)d_in[13]};
    const float* Wr[3] = {(const float*)d_in[8],  (const float*)d_in[11], (const float*)d_in[14]};
    const float* b[3]  = {(const float*)d_in[9],  (const float*)d_in[12], (const float*)d_in[15]};
    float* out_final = (float*)d_out;

    float* g_XW_p;   cudaGetSymbolAddress((void**)&g_XW_p, g_XW);
    float* g_h_p;    cudaGetSymbolAddress((void**)&g_h_p, g_h);
    __nv_bfloat16* xhi_p;  cudaGetSymbolAddress((void**)&xhi_p, g_xhi);
    __nv_bfloat16* xlo_p;  cudaGetSymbolAddress((void**)&xlo_p, g_xlo);
    __nv_bfloat16* bthi_p; cudaGetSymbolAddress((void**)&bthi_p, g_bthi);
    __nv_bfloat16* btlo_p; cudaGetSymbolAddress((void**)&btlo_p, g_btlo);

    cudaFuncSetAttribute(xw_hmma_kernel, cudaFuncAttributeMaxDynamicSharedMemorySize, SMEM_TOT);

    // 1) detect edge_index width
    detect_idx_kernel<<<1, 32>>>((const unsigned int*)ei);

    // 2) edge preprocessing (shared by all layers)
    edge_pre_kernel<<<(NE + 255) / 256, 256>>>(ei, ea, Wp1, bp1, Wp2, bp2);

    // 3) transpose + bf16-split weights once
    for (int l = 0; l < 3; l++) {
        conv_w_kernel<<<(KK * CC * CC + 255) / 256, 256>>>(
            W[l], bthi_p + (size_t)l * NB * CC, btlo_p + (size_t)l * NB * CC);
    }

    // 4) three layers
    const float* act = x;
    dim3 gridXW(NB / 128, (NN + 127) / 128);   // 27 x 157
    dim3 gridRoot(1, (NN + 127) / 128);
    int aggBlocks  = (NE * 32 + 255) / 256;
    int reluBlocks = (NN * CC / 4 + 255) / 256;
    int cvtBlocks  = (NN * CC + 255) / 256;

    for (int l = 0; l < 3; l++) {
        float* outbuf = (l == 2) ? out_final : (g_h_p + (size_t)l * NN * CC);

        // split act into bf16 hi/lo
        convert_act_kernel<<<cvtBlocks, 256>>>(act, xhi_p, xlo_p);

        // XW = act @ Bmat_l via HMMA (split bf16, fp32 accumulate)
        xw_hmma_kernel<<<gridXW, 256, SMEM_TOT>>>(
            xhi_p, xlo_p,
            bthi_p + (size_t)l * NB * CC, btlo_p + (size_t)l * NB * CC,
            g_XW_p);

        // out = act @ Wr_l + b_l   (initializes outbuf)
        sgemm128_kernel<<<gridRoot, 256>>>(act, Wr[l], b[l], outbuf, NN, CC, 1);

        // out[dst] += sum_s bw * XW[src, k_s]
        agg_kernel<<<aggBlocks, 256>>>(g_XW_p, outbuf);

        if (l < 2) {
            relu_kernel<<<reluBlocks, 256>>>(outbuf);
            act = outbuf;
        }
    }
}

// round 10
// speedup vs baseline: 1.8321x; 1.3096x over previous
#include <cuda_runtime.h>
#include <cuda_bf16.h>
#include <cuda_fp16.h>
#include <math.h>
#include <stdint.h>

// Problem constants
#define NN   20000          // nodes
#define NE   320000         // edges
#define CC   128            // channels
#define KK   27             // kernel matrices
#define NB2  (28 * CC)      // 3584 = 27 kernel blocks + 1 root block
#define EDGE_DIM 16
#define MLP_HID  6

// ---------------- static device scratch ----------------
__device__ int   g_idx64;
__device__ int   g_src[NE];
__device__ int   g_dst[NE];
__device__ int   g_kbase[NE];
__device__ float g_bw[NE * 8];           // edge-ordered
// CSR by dst
__device__ int   g_cnt[NN];
__device__ int   g_rowptr[NN + 1];
__device__ int   g_woff[NN];
__device__ int   g_epack[NE];            // src | (kbase<<16), CSR order
__device__ float g_bwc[NE * 8];          // bw, CSR order
// GEMM buffers
__device__ __half g_XWh[(size_t)NN * NB2];            // 143 MB fp16
__device__ float  g_h[2][NN * CC];
__device__ __nv_bfloat16 g_xhi[NN * CC];
__device__ __nv_bfloat16 g_xlo[NN * CC];
__device__ __nv_bfloat16 g_bthi[3][(size_t)NB2 * CC]; // [row=k*128+o][col=cin]
__device__ __nv_bfloat16 g_btlo[3][(size_t)NB2 * CC];

// ---------------- index width detection ----------------
__global__ void detect_idx_kernel(const unsigned int* __restrict__ ei) {
    if (blockIdx.x == 0 && threadIdx.x == 0) {
        int is64 = 1;
        for (int i = 0; i < 4096; i++) {
            if (ei[2 * i + 1] != 0u) { is64 = 0; break; }
        }
        g_idx64 = is64;
    }
}

__global__ void zero_cnt_kernel() {
    int i = blockIdx.x * blockDim.x + threadIdx.x;
    if (i < NN) g_cnt[i] = 0;
}

// ---------------- edge preprocessing: MLP + sigmoid + spline basis + count ----------------
__global__ void edge_pre_kernel(const void* __restrict__ ei_raw,
                                const float* __restrict__ ea,
                                const float* __restrict__ Wp1,
                                const float* __restrict__ bp1,
                                const float* __restrict__ Wp2,
                                const float* __restrict__ bp2) {
    int e = blockIdx.x * blockDim.x + threadIdx.x;
    if (e >= NE) return;

    int s, d;
    if (g_idx64) {
        const long long* p = (const long long*)ei_raw;
        s = (int)p[e];
        d = (int)p[NE + e];
    } else {
        const int* p = (const int*)ei_raw;
        s = p[e];
        d = p[NE + e];
    }
    g_src[e] = s;
    g_dst[e] = d;
    atomicAdd(&g_cnt[d], 1);

    float a[EDGE_DIM];
#pragma unroll
    for (int i = 0; i < EDGE_DIM; i++) a[i] = ea[(size_t)e * EDGE_DIM + i];

    float h[MLP_HID];
#pragma unroll
    for (int j = 0; j < MLP_HID; j++) {
        float z = bp1[j];
#pragma unroll
        for (int i = 0; i < EDGE_DIM; i++) z += a[i] * Wp1[i * MLP_HID + j];
        h[j] = fmaxf(z, 0.0f);
    }

    float fr[3];
    int lo[3];
#pragma unroll
    for (int dd = 0; dd < 3; dd++) {
        float z = bp2[dd];
#pragma unroll
        for (int j = 0; j < MLP_HID; j++) z += h[j] * Wp2[j * 3 + dd];
        float u = 1.0f / (1.0f + expf(-z));
        float v = u * 2.0f;
        float l = fminf(fmaxf(floorf(v), 0.0f), 1.0f);
        lo[dd] = (int)l;
        fr[dd] = v - l;
    }
    g_kbase[e] = lo[0] + 3 * lo[1] + 9 * lo[2];

#pragma unroll
    for (int sb = 0; sb < 8; sb++) {
        float w = ((sb & 1) ? fr[0] : 1.0f - fr[0])
                * ((sb & 2) ? fr[1] : 1.0f - fr[1])
                * ((sb & 4) ? fr[2] : 1.0f - fr[2]);
        g_bw[(size_t)e * 8 + sb] = w;
    }
}

// ---------------- single-block scan: counts -> rowptr, woff ----------------
__global__ void scan_kernel() {
    __shared__ int part[1024];
    const int t = threadIdx.x;
    const int CH = 20;                  // 1024*20 = 20480 >= NN
    int base = t * CH;
    int local[CH];
    int sum = 0;
#pragma unroll
    for (int j = 0; j < CH; j++) {
        int idx = base + j;
        int c = (idx < NN) ? g_cnt[idx] : 0;
        local[j] = sum;
        sum += c;
    }
    part[t] = sum;
    __syncthreads();
    for (int dstep = 1; dstep < 1024; dstep <<= 1) {
        int v = (t >= dstep) ? part[t - dstep] : 0;
        __syncthreads();
        part[t] += v;
        __syncthreads();
    }
    int excl = (t > 0) ? part[t - 1] : 0;
#pragma unroll
    for (int j = 0; j < CH; j++) {
        int idx = base + j;
        if (idx <= NN) {
            int v = excl + local[j];
            g_rowptr[idx] = v;
            if (idx < NN) g_woff[idx] = v;
        }
    }
}

// ---------------- scatter edges into CSR order ----------------
__global__ void scatter_kernel() {
    int e = blockIdx.x * blockDim.x + threadIdx.x;
    if (e >= NE) return;
    int d = g_dst[e];
    int pos = atomicAdd(&g_woff[d], 1);
    g_epack[pos] = g_src[e] | (g_kbase[e] << 16);
#pragma unroll
    for (int t = 0; t < 8; t++) g_bwc[(size_t)pos * 8 + t] = g_bw[(size_t)e * 8 + t];
}

// -------- W [K,Cin,H] fp32 -> Bt rows [k*H+o], cols [Cin], bf16 hi/lo --------
__global__ void conv_w_kernel(const float* __restrict__ W,
                              __nv_bfloat16* __restrict__ hi,
                              __nv_bfloat16* __restrict__ lo) {
    int idx = blockIdx.x * blockDim.x + threadIdx.x;
    if (idx >= KK * CC * CC) return;
    int o = idx & 127;
    int i = (idx >> 7) & 127;
    int k = idx >> 14;
    float v = W[idx];
    __nv_bfloat16 h = __float2bfloat16(v);
    size_t n = (size_t)(k * CC + o) * CC + i;
    hi[n] = h;
    lo[n] = __float2bfloat16(v - __bfloat162float(h));
}

// -------- Wr [Cin,H] appended as block 27 --------
__global__ void conv_wr_kernel(const float* __restrict__ Wr,
                               __nv_bfloat16* __restrict__ hi,
                               __nv_bfloat16* __restrict__ lo) {
    int idx = blockIdx.x * blockDim.x + threadIdx.x;
    if (idx >= CC * CC) return;
    int o = idx & 127;
    int i = idx >> 7;
    float v = Wr[idx];
    __nv_bfloat16 h = __float2bfloat16(v);
    size_t n = (size_t)(27 * CC + o) * CC + i;
    hi[n] = h;
    lo[n] = __float2bfloat16(v - __bfloat162float(h));
}

// -------- activation fp32 -> bf16 hi/lo split (layer 0 only) --------
__global__ void convert_act_kernel(const float* __restrict__ a,
                                   __nv_bfloat16* __restrict__ hi,
                                   __nv_bfloat16* __restrict__ lo) {
    int i = blockIdx.x * blockDim.x + threadIdx.x;
    if (i >= NN * CC) return;
    float v = a[i];
    __nv_bfloat16 h = __float2bfloat16(v);
    hi[i] = h;
    lo[i] = __float2bfloat16(v - __bfloat162float(h));
}

// ================= HMMA (mma.sync bf16) split GEMM: XWh = act @ Bt^T =================
#define SM_AHI 0
#define SM_ALO 32768
#define SM_BHI 65536
#define SM_BLO 98304
#define SMEM_TOT 131072

__device__ __forceinline__ uint32_t smem_u32(const void* p) {
    uint32_t a;
    asm("{ .reg .u64 t; cvta.to.shared.u64 t, %1; cvt.u32.u64 %0, t; }" : "=r"(a) : "l"(p));
    return a;
}
__device__ __forceinline__ uint32_t sw_off(int row, int kc) {
    return (uint32_t)(row * 256 + ((kc ^ (row & 7)) << 4));
}
__device__ __forceinline__ void load_tile(char* smem, int off,
                                          const __nv_bfloat16* __restrict__ src,
                                          int row_base, int row_max, int tid) {
#pragma unroll
    for (int it = 0; it < 8; it++) {
        int idx = it * 256 + tid;
        int row = idx >> 4, kc = idx & 15;
        int grow = row_base + row;
        uint4 v = make_uint4(0u, 0u, 0u, 0u);
        if (grow < row_max)
            v = *(const uint4*)(src + (size_t)grow * CC + kc * 8);
        *(uint4*)(smem + off + sw_off(row, kc)) = v;
    }
}
__device__ __forceinline__ void ldmatrix_x4(uint32_t* r, uint32_t addr) {
    asm volatile("ldmatrix.sync.aligned.m8n8.x4.shared.b16 {%0,%1,%2,%3}, [%4];"
                 : "=r"(r[0]), "=r"(r[1]), "=r"(r[2]), "=r"(r[3]) : "r"(addr));
}
__device__ __forceinline__ void mma16816(float* c, const uint32_t* a, const uint32_t* b) {
    asm volatile(
        "mma.sync.aligned.m16n8k16.row.col.f32.bf16.bf16.f32 "
        "{%0,%1,%2,%3}, {%4,%5,%6,%7}, {%8,%9}, {%0,%1,%2,%3};"
        : "+f"(c[0]), "+f"(c[1]), "+f"(c[2]), "+f"(c[3])
        : "r"(a[0]), "r"(a[1]), "r"(a[2]), "r"(a[3]), "r"(b[0]), "r"(b[1]));
}

__global__ void __launch_bounds__(256, 1)
xw_hmma_kernel(const __nv_bfloat16* __restrict__ xhi,
               const __nv_bfloat16* __restrict__ xlo,
               const __nv_bfloat16* __restrict__ bthi,
               const __nv_bfloat16* __restrict__ btlo,
               __half* __restrict__ XWh) {
    extern __shared__ __align__(1024) char smem[];
    const int tid  = threadIdx.x;
    const int wid  = tid >> 5;
    const int lane = tid & 31;
    const int bn = blockIdx.x * 128;
    const int bm = blockIdx.y * 128;

    load_tile(smem, SM_AHI, xhi,  bm, NN, tid);
    load_tile(smem, SM_ALO, xlo,  bm, NN, tid);
    load_tile(smem, SM_BHI, bthi, bn, NB2, tid);
    load_tile(smem, SM_BLO, btlo, bn, NB2, tid);
    __syncthreads();

    const uint32_t sbase = smem_u32(smem);
    const int m_base = (wid & 1) * 64;
    const int n_base = (wid >> 1) * 32;

    float acc[4][4][4];
#pragma unroll
    for (int mt = 0; mt < 4; mt++)
#pragma unroll
        for (int nt = 0; nt < 4; nt++)
#pragma unroll
            for (int q = 0; q < 4; q++) acc[mt][nt][q] = 0.0f;

    const int a_row_in = (lane & 15);
    const int a_kadd   = (lane >> 4);
    const int b_row_in = ((lane >> 4) << 3) + (lane & 7);
    const int b_kadd   = ((lane >> 3) & 1);

    const int passA[3] = {SM_AHI, SM_ALO, SM_AHI};
    const int passB[3] = {SM_BHI, SM_BHI, SM_BLO};

#pragma unroll
    for (int p = 0; p < 3; p++) {
        const uint32_t abase = sbase + passA[p];
        const uint32_t bbase = sbase + passB[p];
#pragma unroll
        for (int ks = 0; ks < 8; ks++) {
            const int kc = ks * 2;
            uint32_t afrag[4][4];
#pragma unroll
            for (int mt = 0; mt < 4; mt++) {
                int row = m_base + mt * 16 + a_row_in;
                ldmatrix_x4(afrag[mt], abase + sw_off(row, kc + a_kadd));
            }
            uint32_t bfrag[4][2];
#pragma unroll
            for (int g = 0; g < 2; g++) {
                uint32_t r[4];
                int nrow = n_base + g * 16 + b_row_in;
                ldmatrix_x4(r, bbase + sw_off(nrow, kc + b_kadd));
                bfrag[2 * g][0]     = r[0];
                bfrag[2 * g][1]     = r[1];
                bfrag[2 * g + 1][0] = r[2];
                bfrag[2 * g + 1][1] = r[3];
            }
#pragma unroll
            for (int mt = 0; mt < 4; mt++)
#pragma unroll
                for (int nt = 0; nt < 4; nt++)
                    mma16816(acc[mt][nt], afrag[mt], bfrag[nt]);
        }
    }

    // epilogue: fp16 store (half2 = 4B per pair)
    const int qrow = lane >> 2;
    const int qcol = (lane & 3) * 2;
#pragma unroll
    for (int mt = 0; mt < 4; mt++) {
        int r0 = bm + m_base + mt * 16 + qrow;
        int r1 = r0 + 8;
#pragma unroll
        for (int nt = 0; nt < 4; nt++) {
            int col = bn + n_base + nt * 8 + qcol;
            if (r0 < NN) {
                __half2 h = __floats2half2_rn(acc[mt][nt][0], acc[mt][nt][1]);
                *(uint32_t*)(XWh + (size_t)r0 * NB2 + col) = *(uint32_t*)&h;
            }
            if (r1 < NN) {
                __half2 h = __floats2half2_rn(acc[mt][nt][2], acc[mt][nt][3]);
                *(uint32_t*)(XWh + (size_t)r1 * NB2 + col) = *(uint32_t*)&h;
            }
        }
    }
}

// ======== fused aggregation: out[n] = relu?( bias + XWh[n,27] + sum_edges ) ========
// one warp per node; CSR by dst; no atomics. Optionally emits bf16 hi/lo split.
__global__ void __launch_bounds__(256)
agg_csr_kernel(const __half* __restrict__ XWh,
               const float* __restrict__ bias,
               float* __restrict__ out,
               __nv_bfloat16* __restrict__ hi,
               __nv_bfloat16* __restrict__ lo,
               int doRelu, int doSplit) {
    const int n = blockIdx.x * 8 + (threadIdx.x >> 5);
    const int lane = threadIdx.x & 31;
    if (n >= NN) return;
    const int OFF[8] = {0, 1, 3, 4, 9, 10, 12, 13};

    // start from bias + root block (tap 27 of own node)
    float4 bb = *(const float4*)(bias + lane * 4);
    float a0 = bb.x, a1 = bb.y, a2 = bb.z, a3 = bb.w;
    {
        uint2 v = *(const uint2*)(XWh + (size_t)n * NB2 + 27 * CC + lane * 4);
        float2 f0 = __half22float2(*(__half2*)&v.x);
        float2 f1 = __half22float2(*(__half2*)&v.y);
        a0 += f0.x; a1 += f0.y; a2 += f1.x; a3 += f1.y;
    }

    const int beg = g_rowptr[n];
    const int end = g_rowptr[n + 1];
    for (int i = beg; i < end; i++) {
        int packed = g_epack[i];
        int src = packed & 0xffff;
        int kb  = packed >> 16;
        float wv = (lane < 8) ? g_bwc[(size_t)i * 8 + lane] : 0.0f;
        const __half* base = XWh + (size_t)src * NB2 + (size_t)kb * CC + lane * 4;
#pragma unroll
        for (int t = 0; t < 8; t++) {
            float w = __shfl_sync(0xffffffffu, wv, t);
            uint2 v = *(const uint2*)(base + OFF[t] * CC);
            float2 f0 = __half22float2(*(__half2*)&v.x);
            float2 f1 = __half22float2(*(__half2*)&v.y);
            a0 += w * f0.x; a1 += w * f0.y; a2 += w * f1.x; a3 += w * f1.y;
        }
    }

    if (doRelu) {
        a0 = fmaxf(a0, 0.f); a1 = fmaxf(a1, 0.f);
        a2 = fmaxf(a2, 0.f); a3 = fmaxf(a3, 0.f);
    }
    *(float4*)(out + (size_t)n * CC + lane * 4) = make_float4(a0, a1, a2, a3);

    if (doSplit) {
        float vv[4] = {a0, a1, a2, a3};
        __nv_bfloat16 hh[4], ll[4];
#pragma unroll
        for (int q = 0; q < 4; q++) {
            hh[q] = __float2bfloat16(vv[q]);
            ll[q] = __float2bfloat16(vv[q] - __bfloat162float(hh[q]));
        }
        *(uint2*)(hi + (size_t)n * CC + lane * 4) = *(uint2*)hh;
        *(uint2*)(lo + (size_t)n * CC + lane * 4) = *(uint2*)ll;
    }
}

// ---------------- launch ----------------
extern "C" void kernel_launch(void* const* d_in, const int* in_sizes, int n_in,
                              void* d_out, int out_size) {
    const float* x    = (const float*)d_in[0];
    const void*  ei   = d_in[1];
    const float* ea   = (const float*)d_in[2];
    const float* Wp1  = (const float*)d_in[3];
    const float* bp1  = (const float*)d_in[4];
    const float* Wp2  = (const float*)d_in[5];
    const float* bp2  = (const float*)d_in[6];
    const float* W[3]  = {(const float*)d_in[7],  (const float*)d_in[10], (const float*)d_in[13]};
    const float* Wr[3] = {(const float*)d_in[8],  (const float*)d_in[11], (const float*)d_in[14]};
    const float* b[3]  = {(const float*)d_in[9],  (const float*)d_in[12], (const float*)d_in[15]};
    float* out_final = (float*)d_out;

    float* g_h_p;    cudaGetSymbolAddress((void**)&g_h_p, g_h);
    __half* xwh_p;   cudaGetSymbolAddress((void**)&xwh_p, g_XWh);
    __nv_bfloat16* xhi_p;  cudaGetSymbolAddress((void**)&xhi_p, g_xhi);
    __nv_bfloat16* xlo_p;  cudaGetSymbolAddress((void**)&xlo_p, g_xlo);
    __nv_bfloat16* bthi_p; cudaGetSymbolAddress((void**)&bthi_p, g_bthi);
    __nv_bfloat16* btlo_p; cudaGetSymbolAddress((void**)&btlo_p, g_btlo);

    cudaFuncSetAttribute(xw_hmma_kernel, cudaFuncAttributeMaxDynamicSharedMemorySize, SMEM_TOT);

    // 1) detect edge_index width + CSR preprocessing
    detect_idx_kernel<<<1, 32>>>((const unsigned int*)ei);
    zero_cnt_kernel<<<(NN + 255) / 256, 256>>>();
    edge_pre_kernel<<<(NE + 255) / 256, 256>>>(ei, ea, Wp1, bp1, Wp2, bp2);
    scan_kernel<<<1, 1024>>>();
    scatter_kernel<<<(NE + 255) / 256, 256>>>();

    // 2) weights: transpose + bf16-split, root appended as block 27
    for (int l = 0; l < 3; l++) {
        conv_w_kernel<<<(KK * CC * CC + 255) / 256, 256>>>(
            W[l], bthi_p + (size_t)l * NB2 * CC, btlo_p + (size_t)l * NB2 * CC);
        conv_wr_kernel<<<(CC * CC + 255) / 256, 256>>>(
            Wr[l], bthi_p + (size_t)l * NB2 * CC, btlo_p + (size_t)l * NB2 * CC);
    }

    // 3) layer-0 activation split
    convert_act_kernel<<<(NN * CC + 255) / 256, 256>>>(x, xhi_p, xlo_p);

    // 4) three layers
    dim3 gridXW(NB2 / 128, (NN + 127) / 128);   // 28 x 157
    int aggBlocks = (NN + 7) / 8;

    for (int l = 0; l < 3; l++) {
        float* outbuf = (l == 2) ? out_final : (g_h_p + (size_t)l * NN * CC);

        xw_hmma_kernel<<<gridXW, 256, SMEM_TOT>>>(
            xhi_p, xlo_p,
            bthi_p + (size_t)l * NB2 * CC, btlo_p + (size_t)l * NB2 * CC,
            xwh_p);

        agg_csr_kernel<<<aggBlocks, 256>>>(
            xwh_p, b[l], outbuf, xhi_p, xlo_p,
            /*doRelu=*/(l < 2) ? 1 : 0, /*doSplit=*/(l < 2) ? 1 : 0);
    }
}

// round 11
// speedup vs baseline: 1.9808x; 1.0812x over previous
#include <cuda_runtime.h>
#include <cuda_bf16.h>
#include <cuda_fp16.h>
#include <math.h>
#include <stdint.h>

// Problem constants
#define NN   20000          // nodes
#define NE   320000         // edges
#define CC   128            // channels
#define KK   27             // kernel matrices
#define NB2  (28 * CC)      // 3584 = 27 kernel blocks + 1 root block
#define EDGE_DIM 16
#define MLP_HID  6
#define SCAN_BLKS 79        // 79*256 >= NN

// ---------------- static device scratch ----------------
__device__ int   g_idx64;
__device__ int   g_src[NE];
__device__ int   g_dst[NE];
__device__ int   g_kbase[NE];
__device__ float g_bw[NE * 8];           // edge-ordered
// CSR by dst
__device__ int   g_cnt[NN];
__device__ int   g_rowptr[NN + 1];
__device__ int   g_woff[NN];
__device__ int   g_bsum[SCAN_BLKS];
__device__ int   g_bpre[SCAN_BLKS];
__device__ int   g_epack[NE];            // src | (kbase<<16), CSR order
__device__ float g_bwc[NE * 8];          // bw, CSR order
// GEMM buffers
__device__ __half g_XWh[(size_t)NN * NB2];            // 143 MB fp16
__device__ float  g_h[2][NN * CC];
__device__ __nv_bfloat16 g_xhi[NN * CC];
__device__ __nv_bfloat16 g_xlo[NN * CC];
__device__ __nv_bfloat16 g_bthi[3][(size_t)NB2 * CC]; // [row=k*128+o][col=cin]
__device__ __nv_bfloat16 g_btlo[3][(size_t)NB2 * CC];

// ---------------- index width detection ----------------
__global__ void detect_idx_kernel(const unsigned int* __restrict__ ei) {
    if (blockIdx.x == 0 && threadIdx.x == 0) {
        int is64 = 1;
        for (int i = 0; i < 4096; i++) {
            if (ei[2 * i + 1] != 0u) { is64 = 0; break; }
        }
        g_idx64 = is64;
    }
}

__global__ void zero_cnt_kernel() {
    int i = blockIdx.x * blockDim.x + threadIdx.x;
    if (i < NN) g_cnt[i] = 0;
}

// ---------------- edge preprocessing: MLP + sigmoid + spline basis + count ----------------
__global__ void edge_pre_kernel(const void* __restrict__ ei_raw,
                                const float* __restrict__ ea,
                                const float* __restrict__ Wp1,
                                const float* __restrict__ bp1,
                                const float* __restrict__ Wp2,
                                const float* __restrict__ bp2) {
    int e = blockIdx.x * blockDim.x + threadIdx.x;
    if (e >= NE) return;

    int s, d;
    if (g_idx64) {
        const long long* p = (const long long*)ei_raw;
        s = (int)p[e];
        d = (int)p[NE + e];
    } else {
        const int* p = (const int*)ei_raw;
        s = p[e];
        d = p[NE + e];
    }
    g_src[e] = s;
    g_dst[e] = d;
    atomicAdd(&g_cnt[d], 1);

    float a[EDGE_DIM];
#pragma unroll
    for (int i = 0; i < EDGE_DIM; i++) a[i] = ea[(size_t)e * EDGE_DIM + i];

    float h[MLP_HID];
#pragma unroll
    for (int j = 0; j < MLP_HID; j++) {
        float z = bp1[j];
#pragma unroll
        for (int i = 0; i < EDGE_DIM; i++) z += a[i] * Wp1[i * MLP_HID + j];
        h[j] = fmaxf(z, 0.0f);
    }

    float fr[3];
    int lo[3];
#pragma unroll
    for (int dd = 0; dd < 3; dd++) {
        float z = bp2[dd];
#pragma unroll
        for (int j = 0; j < MLP_HID; j++) z += h[j] * Wp2[j * 3 + dd];
        float u = 1.0f / (1.0f + expf(-z));
        float v = u * 2.0f;
        float l = fminf(fmaxf(floorf(v), 0.0f), 1.0f);
        lo[dd] = (int)l;
        fr[dd] = v - l;
    }
    g_kbase[e] = lo[0] + 3 * lo[1] + 9 * lo[2];

#pragma unroll
    for (int sb = 0; sb < 8; sb++) {
        float w = ((sb & 1) ? fr[0] : 1.0f - fr[0])
                * ((sb & 2) ? fr[1] : 1.0f - fr[1])
                * ((sb & 4) ? fr[2] : 1.0f - fr[2]);
        g_bw[(size_t)e * 8 + sb] = w;
    }
}

// ---------------- 3-phase scan: counts -> rowptr, woff ----------------
__global__ void blocksum_kernel() {
    __shared__ int sh[256];
    int idx = blockIdx.x * 256 + threadIdx.x;
    int c = (idx < NN) ? g_cnt[idx] : 0;
    sh[threadIdx.x] = c;
    __syncthreads();
    for (int s = 128; s > 0; s >>= 1) {
        if (threadIdx.x < s) sh[threadIdx.x] += sh[threadIdx.x + s];
        __syncthreads();
    }
    if (threadIdx.x == 0) g_bsum[blockIdx.x] = sh[0];
}

__global__ void scanpart_kernel() {
    // single block of 128; scan SCAN_BLKS partials (exclusive)
    __shared__ int sh[128];
    int t = threadIdx.x;
    int v = (t < SCAN_BLKS) ? g_bsum[t] : 0;
    sh[t] = v;
    __syncthreads();
    for (int d = 1; d < 128; d <<= 1) {
        int u = (t >= d) ? sh[t - d] : 0;
        __syncthreads();
        sh[t] += u;
        __syncthreads();
    }
    if (t < SCAN_BLKS) g_bpre[t] = sh[t] - v;   // exclusive
    if (t == 0) g_rowptr[NN] = NE;
}

__global__ void rowptr_kernel() {
    __shared__ int sh[256];
    int idx = blockIdx.x * 256 + threadIdx.x;
    int t = threadIdx.x;
    int c = (idx < NN) ? g_cnt[idx] : 0;
    sh[t] = c;
    __syncthreads();
    for (int d = 1; d < 256; d <<= 1) {
        int u = (t >= d) ? sh[t - d] : 0;
        __syncthreads();
        sh[t] += u;
        __syncthreads();
    }
    if (idx < NN) {
        int excl = g_bpre[blockIdx.x] + sh[t] - c;
        g_rowptr[idx] = excl;
        g_woff[idx] = excl;
    }
}

// ---------------- scatter edges into CSR order ----------------
__global__ void scatter_kernel() {
    int e = blockIdx.x * blockDim.x + threadIdx.x;
    if (e >= NE) return;
    int d = g_dst[e];
    int pos = atomicAdd(&g_woff[d], 1);
    g_epack[pos] = g_src[e] | (g_kbase[e] << 16);
#pragma unroll
    for (int t = 0; t < 8; t++) g_bwc[(size_t)pos * 8 + t] = g_bw[(size_t)e * 8 + t];
}

// -------- W [K,Cin,H] fp32 -> Bt rows [k*H+o], cols [Cin], bf16 hi/lo --------
__global__ void conv_w_kernel(const float* __restrict__ W,
                              __nv_bfloat16* __restrict__ hi,
                              __nv_bfloat16* __restrict__ lo) {
    int idx = blockIdx.x * blockDim.x + threadIdx.x;
    if (idx >= KK * CC * CC) return;
    int o = idx & 127;
    int i = (idx >> 7) & 127;
    int k = idx >> 14;
    float v = W[idx];
    __nv_bfloat16 h = __float2bfloat16(v);
    size_t n = (size_t)(k * CC + o) * CC + i;
    hi[n] = h;
    lo[n] = __float2bfloat16(v - __bfloat162float(h));
}

// -------- Wr [Cin,H] appended as block 27 --------
__global__ void conv_wr_kernel(const float* __restrict__ Wr,
                               __nv_bfloat16* __restrict__ hi,
                               __nv_bfloat16* __restrict__ lo) {
    int idx = blockIdx.x * blockDim.x + threadIdx.x;
    if (idx >= CC * CC) return;
    int o = idx & 127;
    int i = idx >> 7;
    float v = Wr[idx];
    __nv_bfloat16 h = __float2bfloat16(v);
    size_t n = (size_t)(27 * CC + o) * CC + i;
    hi[n] = h;
    lo[n] = __float2bfloat16(v - __bfloat162float(h));
}

// -------- activation fp32 -> bf16 hi/lo split (layer 0 only) --------
__global__ void convert_act_kernel(const float* __restrict__ a,
                                   __nv_bfloat16* __restrict__ hi,
                                   __nv_bfloat16* __restrict__ lo) {
    int i = blockIdx.x * blockDim.x + threadIdx.x;
    if (i >= NN * CC) return;
    float v = a[i];
    __nv_bfloat16 h = __float2bfloat16(v);
    hi[i] = h;
    lo[i] = __float2bfloat16(v - __bfloat162float(h));
}

// ================= HMMA (mma.sync bf16) split GEMM: XWh = act @ Bt^T =================
// 96KB smem (3 buffers) -> 2 CTAs/SM for load/compute overlap across CTAs.
// Buffer X holds Alo for passes 1-2, then is overwritten with Blo for pass 3.
#define SM_AHI 0
#define SM_BHI 32768
#define SM_X   65536
#define SMEM_TOT 98304

__device__ __forceinline__ uint32_t smem_u32(const void* p) {
    uint32_t a;
    asm("{ .reg .u64 t; cvta.to.shared.u64 t, %1; cvt.u32.u64 %0, t; }" : "=r"(a) : "l"(p));
    return a;
}
__device__ __forceinline__ uint32_t sw_off(int row, int kc) {
    return (uint32_t)(row * 256 + ((kc ^ (row & 7)) << 4));
}
__device__ __forceinline__ void load_tile(char* smem, int off,
                                          const __nv_bfloat16* __restrict__ src,
                                          int row_base, int row_max, int tid) {
#pragma unroll
    for (int it = 0; it < 8; it++) {
        int idx = it * 256 + tid;
        int row = idx >> 4, kc = idx & 15;
        int grow = row_base + row;
        uint4 v = make_uint4(0u, 0u, 0u, 0u);
        if (grow < row_max)
            v = *(const uint4*)(src + (size_t)grow * CC + kc * 8);
        *(uint4*)(smem + off + sw_off(row, kc)) = v;
    }
}
__device__ __forceinline__ void ldmatrix_x4(uint32_t* r, uint32_t addr) {
    asm volatile("ldmatrix.sync.aligned.m8n8.x4.shared.b16 {%0,%1,%2,%3}, [%4];"
                 : "=r"(r[0]), "=r"(r[1]), "=r"(r[2]), "=r"(r[3]) : "r"(addr));
}
__device__ __forceinline__ void mma16816(float* c, const uint32_t* a, const uint32_t* b) {
    asm volatile(
        "mma.sync.aligned.m16n8k16.row.col.f32.bf16.bf16.f32 "
        "{%0,%1,%2,%3}, {%4,%5,%6,%7}, {%8,%9}, {%0,%1,%2,%3};"
        : "+f"(c[0]), "+f"(c[1]), "+f"(c[2]), "+f"(c[3])
        : "r"(a[0]), "r"(a[1]), "r"(a[2]), "r"(a[3]), "r"(b[0]), "r"(b[1]));
}

__global__ void __launch_bounds__(256, 2)
xw_hmma_kernel(const __nv_bfloat16* __restrict__ xhi,
               const __nv_bfloat16* __restrict__ xlo,
               const __nv_bfloat16* __restrict__ bthi,
               const __nv_bfloat16* __restrict__ btlo,
               __half* __restrict__ XWh) {
    extern __shared__ __align__(1024) char smem[];
    const int tid  = threadIdx.x;
    const int wid  = tid >> 5;
    const int lane = tid & 31;
    const int bn = blockIdx.x * 128;
    const int bm = blockIdx.y * 128;

    load_tile(smem, SM_AHI, xhi,  bm, NN, tid);
    load_tile(smem, SM_BHI, bthi, bn, NB2, tid);
    load_tile(smem, SM_X,   xlo,  bm, NN, tid);
    __syncthreads();

    const uint32_t sbase = smem_u32(smem);
    const int m_base = (wid & 1) * 64;
    const int n_base = (wid >> 1) * 32;

    float acc[4][4][4];
#pragma unroll
    for (int mt = 0; mt < 4; mt++)
#pragma unroll
        for (int nt = 0; nt < 4; nt++)
#pragma unroll
            for (int q = 0; q < 4; q++) acc[mt][nt][q] = 0.0f;

    const int a_row_in = (lane & 15);
    const int a_kadd   = (lane >> 4);
    const int b_row_in = ((lane >> 4) << 3) + (lane & 7);
    const int b_kadd   = ((lane >> 3) & 1);

    // pass loop body as a lambda-free macro-ish function
    auto run_pass = [&](int offA, int offB) {
        const uint32_t abase = sbase + offA;
        const uint32_t bbase = sbase + offB;
#pragma unroll
        for (int ks = 0; ks < 8; ks++) {
            const int kc = ks * 2;
            uint32_t afrag[4][4];
#pragma unroll
            for (int mt = 0; mt < 4; mt++) {
                int row = m_base + mt * 16 + a_row_in;
                ldmatrix_x4(afrag[mt], abase + sw_off(row, kc + a_kadd));
            }
            uint32_t bfrag[4][2];
#pragma unroll
            for (int g = 0; g < 2; g++) {
                uint32_t r[4];
                int nrow = n_base + g * 16 + b_row_in;
                ldmatrix_x4(r, bbase + sw_off(nrow, kc + b_kadd));
                bfrag[2 * g][0]     = r[0];
                bfrag[2 * g][1]     = r[1];
                bfrag[2 * g + 1][0] = r[2];
                bfrag[2 * g + 1][1] = r[3];
            }
#pragma unroll
            for (int mt = 0; mt < 4; mt++)
#pragma unroll
                for (int nt = 0; nt < 4; nt++)
                    mma16816(acc[mt][nt], afrag[mt], bfrag[nt]);
        }
    };

    run_pass(SM_AHI, SM_BHI);   // Ahi * Bhi
    run_pass(SM_X,   SM_BHI);   // Alo * Bhi
    __syncthreads();
    load_tile(smem, SM_X, btlo, bn, NB2, tid);   // X := Blo
    __syncthreads();
    run_pass(SM_AHI, SM_X);     // Ahi * Blo

    // epilogue: fp16 store (half2 = 4B per pair)
    const int qrow = lane >> 2;
    const int qcol = (lane & 3) * 2;
#pragma unroll
    for (int mt = 0; mt < 4; mt++) {
        int r0 = bm + m_base + mt * 16 + qrow;
        int r1 = r0 + 8;
#pragma unroll
        for (int nt = 0; nt < 4; nt++) {
            int col = bn + n_base + nt * 8 + qcol;
            if (r0 < NN) {
                __half2 h = __floats2half2_rn(acc[mt][nt][0], acc[mt][nt][1]);
                *(uint32_t*)(XWh + (size_t)r0 * NB2 + col) = *(uint32_t*)&h;
            }
            if (r1 < NN) {
                __half2 h = __floats2half2_rn(acc[mt][nt][2], acc[mt][nt][3]);
                *(uint32_t*)(XWh + (size_t)r1 * NB2 + col) = *(uint32_t*)&h;
            }
        }
    }
}

// ======== fused aggregation: out[n] = relu?( bias + XWh[n,27] + sum_edges ) ========
__global__ void __launch_bounds__(256)
agg_csr_kernel(const __half* __restrict__ XWh,
               const float* __restrict__ bias,
               float* __restrict__ out,
               __nv_bfloat16* __restrict__ hi,
               __nv_bfloat16* __restrict__ lo,
               int doRelu, int doSplit) {
    const int n = blockIdx.x * 8 + (threadIdx.x >> 5);
    const int lane = threadIdx.x & 31;
    if (n >= NN) return;
    const int OFF[8] = {0, 1, 3, 4, 9, 10, 12, 13};

    float4 bb = *(const float4*)(bias + lane * 4);
    float a0 = bb.x, a1 = bb.y, a2 = bb.z, a3 = bb.w;
    {
        uint2 v = *(const uint2*)(XWh + (size_t)n * NB2 + 27 * CC + lane * 4);
        float2 f0 = __half22float2(*(__half2*)&v.x);
        float2 f1 = __half22float2(*(__half2*)&v.y);
        a0 += f0.x; a1 += f0.y; a2 += f1.x; a3 += f1.y;
    }

    const int beg = g_rowptr[n];
    const int end = g_rowptr[n + 1];
    for (int i = beg; i < end; i++) {
        int packed = g_epack[i];
        int src = packed & 0xffff;
        int kb  = packed >> 16;
        float wv = (lane < 8) ? g_bwc[(size_t)i * 8 + lane] : 0.0f;
        const __half* base = XWh + (size_t)src * NB2 + (size_t)kb * CC + lane * 4;
#pragma unroll
        for (int t = 0; t < 8; t++) {
            float w = __shfl_sync(0xffffffffu, wv, t);
            uint2 v = *(const uint2*)(base + OFF[t] * CC);
            float2 f0 = __half22float2(*(__half2*)&v.x);
            float2 f1 = __half22float2(*(__half2*)&v.y);
            a0 += w * f0.x; a1 += w * f0.y; a2 += w * f1.x; a3 += w * f1.y;
        }
    }

    if (doRelu) {
        a0 = fmaxf(a0, 0.f); a1 = fmaxf(a1, 0.f);
        a2 = fmaxf(a2, 0.f); a3 = fmaxf(a3, 0.f);
    }
    *(float4*)(out + (size_t)n * CC + lane * 4) = make_float4(a0, a1, a2, a3);

    if (doSplit) {
        float vv[4] = {a0, a1, a2, a3};
        __nv_bfloat16 hh[4], ll[4];
#pragma unroll
        for (int q = 0; q < 4; q++) {
            hh[q] = __float2bfloat16(vv[q]);
            ll[q] = __float2bfloat16(vv[q] - __bfloat162float(hh[q]));
        }
        *(uint2*)(hi + (size_t)n * CC + lane * 4) = *(uint2*)hh;
        *(uint2*)(lo + (size_t)n * CC + lane * 4) = *(uint2*)ll;
    }
}

// ---------------- launch ----------------
extern "C" void kernel_launch(void* const* d_in, const int* in_sizes, int n_in,
                              void* d_out, int out_size) {
    const float* x    = (const float*)d_in[0];
    const void*  ei   = d_in[1];
    const float* ea   = (const float*)d_in[2];
    const float* Wp1  = (const float*)d_in[3];
    const float* bp1  = (const float*)d_in[4];
    const float* Wp2  = (const float*)d_in[5];
    const float* bp2  = (const float*)d_in[6];
    const float* W[3]  = {(const float*)d_in[7],  (const float*)d_in[10], (const float*)d_in[13]};
    const float* Wr[3] = {(const float*)d_in[8],  (const float*)d_in[11], (const float*)d_in[14]};
    const float* b[3]  = {(const float*)d_in[9],  (const float*)d_in[12], (const float*)d_in[15]};
    float* out_final = (float*)d_out;

    float* g_h_p;    cudaGetSymbolAddress((void**)&g_h_p, g_h);
    __half* xwh_p;   cudaGetSymbolAddress((void**)&xwh_p, g_XWh);
    __nv_bfloat16* xhi_p;  cudaGetSymbolAddress((void**)&xhi_p, g_xhi);
    __nv_bfloat16* xlo_p;  cudaGetSymbolAddress((void**)&xlo_p, g_xlo);
    __nv_bfloat16* bthi_p; cudaGetSymbolAddress((void**)&bthi_p, g_bthi);
    __nv_bfloat16* btlo_p; cudaGetSymbolAddress((void**)&btlo_p, g_btlo);

    cudaFuncSetAttribute(xw_hmma_kernel, cudaFuncAttributeMaxDynamicSharedMemorySize, SMEM_TOT);

    // 1) edge preprocessing + CSR build
    detect_idx_kernel<<<1, 32>>>((const unsigned int*)ei);
    zero_cnt_kernel<<<(NN + 255) / 256, 256>>>();
    edge_pre_kernel<<<(NE + 255) / 256, 256>>>(ei, ea, Wp1, bp1, Wp2, bp2);
    blocksum_kernel<<<SCAN_BLKS, 256>>>();
    scanpart_kernel<<<1, 128>>>();
    rowptr_kernel<<<SCAN_BLKS, 256>>>();
    scatter_kernel<<<(NE + 255) / 256, 256>>>();

    // 2) weights: transpose + bf16-split, root appended as block 27
    for (int l = 0; l < 3; l++) {
        conv_w_kernel<<<(KK * CC * CC + 255) / 256, 256>>>(
            W[l], bthi_p + (size_t)l * NB2 * CC, btlo_p + (size_t)l * NB2 * CC);
        conv_wr_kernel<<<(CC * CC + 255) / 256, 256>>>(
            Wr[l], bthi_p + (size_t)l * NB2 * CC, btlo_p + (size_t)l * NB2 * CC);
    }

    // 3) layer-0 activation split
    convert_act_kernel<<<(NN * CC + 255) / 256, 256>>>(x, xhi_p, xlo_p);

    // 4) three layers
    dim3 gridXW(NB2 / 128, (NN + 127) / 128);   // 28 x 157
    int aggBlocks = (NN + 7) / 8;

    for (int l = 0; l < 3; l++) {
        float* outbuf = (l == 2) ? out_final : (g_h_p + (size_t)l * NN * CC);

        xw_hmma_kernel<<<gridXW, 256, SMEM_TOT>>>(
            xhi_p, xlo_p,
            bthi_p + (size_t)l * NB2 * CC, btlo_p + (size_t)l * NB2 * CC,
            xwh_p);

        agg_csr_kernel<<<aggBlocks, 256>>>(
            xwh_p, b[l], outbuf, xhi_p, xlo_p,
            /*doRelu=*/(l < 2) ? 1 : 0, /*doSplit=*/(l < 2) ? 1 : 0);
    }
}